// round 2
// baseline (speedup 1.0000x reference)
#include <cuda_runtime.h>
#include <cstdint>
#include <math.h>

#define T_STEPS 1024
#define BATCH   16
#define DIM     1024
#define BD      (BATCH*DIM)           /* 16384 */
#define TBD     (T_STEPS*BATCH*DIM)   /* 16777216 */
#define NCTA    128
#define NTHR    256
#define EPSF    1e-8f
#define MAXR    0.999f

// ---------------- device scratch (no allocations allowed) -------------------
__device__ float    g_G[TBD];          // x @ W_x^T + b
__device__ float    g_h[2][BD];        // double-buffered hidden state [b][d]
__device__ float    g_u[DIM];
__device__ float    g_v[DIM];
__device__ float    g_vraw[DIM];
__device__ float    g_uraw[DIM];
__device__ unsigned g_flag[NCTA];
__device__ unsigned g_gen;

// ---------------- low-level helpers ----------------------------------------
__device__ __forceinline__ void cp_async16(void* dst, const void* src) {
    unsigned s = (unsigned)__cvta_generic_to_shared(dst);
    asm volatile("cp.async.cg.shared.global [%0], [%1], 16;" :: "r"(s), "l"(src));
}
__device__ __forceinline__ void cp_commit() { asm volatile("cp.async.commit_group;"); }
__device__ __forceinline__ void cp_wait0()  { asm volatile("cp.async.wait_group 0;"); }

__device__ __forceinline__ unsigned ld_acq(const unsigned* p) {
    unsigned v;
    asm volatile("ld.acquire.gpu.u32 %0, [%1];" : "=r"(v) : "l"(p) : "memory");
    return v;
}
__device__ __forceinline__ void st_rel(unsigned* p, unsigned v) {
    asm volatile("st.release.gpu.u32 [%0], %1;" :: "l"(p), "r"(v) : "memory");
}

// Flag-array grid barrier. Monotonic targets survive graph replays.
// CTA0's warp 0 polls all flags (4 per lane), then publishes g_gen.
__device__ __forceinline__ void grid_barrier(int c, unsigned target) {
    __syncthreads();
    if (threadIdx.x < 32) {
        if (threadIdx.x == 0) {
            __threadfence();
            st_rel(&g_flag[c], target);
        }
        if (c == 0) {
            unsigned ok;
            do {
                ok = 1u;
#pragma unroll
                for (int q = 0; q < 4; ++q)
                    ok &= (unsigned)(ld_acq(&g_flag[threadIdx.x + 32*q]) >= target);
            } while (!__all_sync(0xffffffffu, ok));
            if (threadIdx.x == 0) st_rel(&g_gen, target);
        } else if (threadIdx.x == 0) {
            while (ld_acq(&g_gen) < target) { }
        }
    }
    __syncthreads();
}

// ---------------- GEMM: g_G = X[16384,1024] @ Wx[1024,1024]^T + bias --------
__global__ void __launch_bounds__(256) gemm_kernel(
    const float* __restrict__ X, const float* __restrict__ Wx,
    const float* __restrict__ bias)
{
    __shared__ float As[8][128];
    __shared__ float Bs[8][128];
    const int tid  = threadIdx.x;
    const int bn0  = blockIdx.x * 128;
    const int bm0  = blockIdx.y * 128;
    const int tm   = tid & 15;
    const int tn   = tid >> 4;
    const int lrow = tid >> 1;
    const int lk   = (tid & 1) * 4;
    const float* Ap = X  + (size_t)(bm0 + lrow) * DIM + lk;
    const float* Bp = Wx + (size_t)(bn0 + lrow) * DIM + lk;

    float acc[8][8];
#pragma unroll
    for (int i = 0; i < 8; ++i)
#pragma unroll
        for (int j = 0; j < 8; ++j) acc[i][j] = 0.f;

    for (int k0 = 0; k0 < DIM; k0 += 8) {
        float4 av = *(const float4*)(Ap + k0);
        float4 bv = *(const float4*)(Bp + k0);
        __syncthreads();
        As[lk+0][lrow] = av.x; As[lk+1][lrow] = av.y;
        As[lk+2][lrow] = av.z; As[lk+3][lrow] = av.w;
        Bs[lk+0][lrow] = bv.x; Bs[lk+1][lrow] = bv.y;
        Bs[lk+2][lrow] = bv.z; Bs[lk+3][lrow] = bv.w;
        __syncthreads();
#pragma unroll
        for (int kk = 0; kk < 8; ++kk) {
            float af[8], bf[8];
#pragma unroll
            for (int i = 0; i < 4; ++i) {
                af[i]   = As[kk][tm*4 + i];
                af[4+i] = As[kk][64 + tm*4 + i];
                bf[i]   = Bs[kk][tn*4 + i];
                bf[4+i] = Bs[kk][64 + tn*4 + i];
            }
#pragma unroll
            for (int i = 0; i < 8; ++i)
#pragma unroll
                for (int j = 0; j < 8; ++j) acc[i][j] += af[i] * bf[j];
        }
    }
    float bf2[8];
#pragma unroll
    for (int i = 0; i < 4; ++i) {
        bf2[i]   = bias[bn0 + tn*4 + i];
        bf2[4+i] = bias[bn0 + 64 + tn*4 + i];
    }
#pragma unroll
    for (int i = 0; i < 8; ++i) {
        int m = bm0 + ((i < 4) ? (tm*4 + i) : (64 + tm*4 + (i - 4)));
        float4 o0, o1;
        o0.x = acc[i][0] + bf2[0]; o0.y = acc[i][1] + bf2[1];
        o0.z = acc[i][2] + bf2[2]; o0.w = acc[i][3] + bf2[3];
        o1.x = acc[i][4] + bf2[4]; o1.y = acc[i][5] + bf2[5];
        o1.z = acc[i][6] + bf2[6]; o1.w = acc[i][7] + bf2[7];
        *(float4*)&g_G[(size_t)m * DIM + bn0 + tn*4]      = o0;
        *(float4*)&g_G[(size_t)m * DIM + bn0 + 64 + tn*4] = o1;
    }
}

// ---------------- persistent: power iter + recurrence + gating --------------
// smem: h_sm[16384] | red[8*16*36] | nrm[256]   -> 84992 bytes
#define SMEM_RNN_BYTES ((16384 + 8*16*36 + 256) * 4)

__global__ void __launch_bounds__(NTHR, 1) rnn_kernel(
    const float* __restrict__ z,   const float* __restrict__ h0,
    const float* __restrict__ Wh,  const float* __restrict__ logr,
    const float* __restrict__ u0,  float* __restrict__ out)
{
    extern __shared__ float sm[];
    float* h_sm = sm;                    // 16384 floats [b][k]
    float* red  = sm + 16384;            // 4608 floats
    float* nrm  = sm + 16384 + 4608;     // 256 floats

    const int c    = blockIdx.x;
    const int tid  = threadIdx.x;
    const int lane = tid & 31;
    const int w    = tid >> 5;           // 8 warps
    const int bg   = w & 3;              // batch group (4 batches)
    const int og   = w >> 2;             // dim group (4 dims)

    float* outs  = out;
    float* h_all = out + TBD;

    unsigned bt = ld_acq(&g_gen);        // monotonic base across replays

    // ---- (a) init: h0 -> g_h[0] and h_all[0]; u0 -> g_u ----
    if (tid < 128) {
        int i = c*128 + tid;
        float v = h0[i];
        g_h[0][i] = v;
        h_all[i]  = v;
    }
    if (tid < 8) g_u[c*8 + tid] = u0[c*8 + tid];
    grid_barrier(c, ++bt);

    // ---- (b) 3-step power iteration ----
    float sigma = 0.f;
    for (int it = 0; it < 3; ++it) {
        {   // vraw = Wh^T u : CTA owns columns [8c, 8c+8)
            int jj = tid & 7, rc = tid >> 3;
            const float* col = Wh + 8*c + jj;
            float p = 0.f;
            for (int ii = 0; ii < 32; ++ii) {
                int i = rc*32 + ii;
                p += __ldg(col + (size_t)i*DIM) * __ldcg(&g_u[i]);
            }
            nrm[tid] = p;
        }
        __syncthreads();
        if (tid < 8) {
            float s = 0.f;
            for (int rc = 0; rc < 32; ++rc) s += nrm[tid + 8*rc];
            g_vraw[8*c + tid] = s;
        }
        grid_barrier(c, ++bt);
        {   // normalize v (each CTA redundantly, deterministic)
            float p = 0.f;
            for (int i = tid; i < DIM; i += NTHR) { float x = __ldcg(&g_vraw[i]); p += x*x; }
            nrm[tid] = p; __syncthreads();
            for (int o = 128; o > 0; o >>= 1) {
                if (tid < o) nrm[tid] += nrm[tid + o];
                __syncthreads();
            }
            float inv = 1.f / (sqrtf(nrm[0]) + EPSF);
            __syncthreads();
            if (tid < 8) g_v[8*c + tid] = __ldcg(&g_vraw[8*c + tid]) * inv;
        }
        grid_barrier(c, ++bt);
        {   // uraw = Wh v : warp per row
            int r = 8*c + w;
            const float* row = Wh + (size_t)r*DIM;
            float p = 0.f;
            for (int j = 0; j < 32; ++j) {
                int k = lane + 32*j;
                p += __ldg(row + k) * __ldcg(&g_v[k]);
            }
#pragma unroll
            for (int o = 16; o; o >>= 1) p += __shfl_xor_sync(0xffffffffu, p, o);
            if (lane == 0) g_uraw[r] = p;
        }
        grid_barrier(c, ++bt);
        {   // normalize u / sigma
            float p = 0.f;
            for (int i = tid; i < DIM; i += NTHR) { float x = __ldcg(&g_uraw[i]); p += x*x; }
            nrm[tid] = p; __syncthreads();
            for (int o = 128; o > 0; o >>= 1) {
                if (tid < o) nrm[tid] += nrm[tid + o];
                __syncthreads();
            }
            float s2 = nrm[0];
            __syncthreads();
            if (it < 2) {
                float inv = 1.f / (sqrtf(s2) + EPSF);
                if (tid < 8) g_u[8*c + tid] = __ldcg(&g_uraw[8*c + tid]) * inv;
                grid_barrier(c, ++bt);
            } else {
                // sigma = |u . (Wh v)| = ||uraw||^2 / (||uraw|| + eps)
                sigma = s2 / (sqrtf(s2) + EPSF);
            }
        }
    }

    // ---- (c) load W_eff slice into registers (time-invariant) ----
    // lane holds k = lane + 32*j ; dims d = c*8 + og*4 + oi
    float wreg[4][32];
#pragma unroll
    for (int oi = 0; oi < 4; ++oi) {
        int d = c*8 + og*4 + oi;
        float lr  = __ldg(&logr[d]);
        float rad = MAXR / (1.f + expf(-lr));
        float mult = rad / (sigma + EPSF);
        const float* row = Wh + (size_t)d*DIM;
#pragma unroll
        for (int j = 0; j < 32; ++j)
            wreg[oi][j] = __ldg(row + lane + 32*j) * mult;
    }

    // epilogue mapping: lanes 0..15, d varies fastest for coalescing
    const int eoi = lane & 3;
    const int ebi = lane >> 2;
    const int eb  = 4*bg + ebi;
    const int ed  = c*8 + og*4 + eoi;
    const int eidx0 = eb*DIM + ed;
    float* myred = red + w*576;

    // ---- (d) recurrence ----
    int p = 0;
    for (int t = 0; t < T_STEPS; ++t) {
        grid_barrier(c, ++bt);          // all g_h[p] writes visible

        // stage h (64 KB) into smem via cp.async (L2 path)
        const float* src = g_h[p];
#pragma unroll
        for (int i = 0; i < 16; ++i) {
            int chunk = i*NTHR + tid;   // 4096 x 16B
            cp_async16(&h_sm[chunk*4], src + chunk*4);
        }
        cp_commit();

        // prefetch G and z while cp.async is in flight
        float gpre = 0.f, zpre = 0.f;
        size_t gi = (size_t)t*BD + eidx0;
        if (lane < 16) {
            gpre = __ldg(&g_G[gi]);
            zpre = __ldg(&z[gi]);
        }
        cp_wait0();
        __syncthreads();

        // 4 batch x 4 dim register micro-tile, k split across lanes
        float acc[4][4];
#pragma unroll
        for (int bi = 0; bi < 4; ++bi)
#pragma unroll
            for (int oi = 0; oi < 4; ++oi) acc[bi][oi] = 0.f;

        const float* hb = h_sm + 4*bg*DIM + lane;
#pragma unroll
        for (int j = 0; j < 32; ++j) {
            float h0v = hb[0*DIM + 32*j];
            float h1v = hb[1*DIM + 32*j];
            float h2v = hb[2*DIM + 32*j];
            float h3v = hb[3*DIM + 32*j];
#pragma unroll
            for (int oi = 0; oi < 4; ++oi) {
                float wv = wreg[oi][j];
                acc[0][oi] += wv * h0v;
                acc[1][oi] += wv * h1v;
                acc[2][oi] += wv * h2v;
                acc[3][oi] += wv * h3v;
            }
        }

        // cross-lane (k) reduction via padded smem, warp-local
#pragma unroll
        for (int bi = 0; bi < 4; ++bi)
#pragma unroll
            for (int oi = 0; oi < 4; ++oi)
                myred[(oi + 4*bi)*36 + lane] = acc[bi][oi];
        __syncwarp();

        if (lane < 16) {
            const float* rrow = myred + lane*36;
            float4 s4 = make_float4(0.f, 0.f, 0.f, 0.f);
#pragma unroll
            for (int q = 0; q < 8; ++q) {
                float4 v = *(const float4*)(rrow + q*4);
                s4.x += v.x; s4.y += v.y; s4.z += v.z; s4.w += v.w;
            }
            float s  = (s4.x + s4.y) + (s4.z + s4.w);
            float hn = tanhf(s + gpre);
            float ov = hn * (zpre / (1.f + expf(-zpre)));   // h * silu(z)
            outs[gi]       = ov;
            h_all[gi + BD] = hn;
            __stcg(&g_h[p ^ 1][eidx0], hn);
        }
        p ^= 1;
    }
}

// ---------------- launch -----------------------------------------------------
extern "C" void kernel_launch(void* const* d_in, const int* in_sizes, int n_in,
                              void* d_out, int out_size) {
    const float* x    = (const float*)d_in[0];
    const float* z    = (const float*)d_in[1];
    const float* h0   = (const float*)d_in[2];
    const float* Wx   = (const float*)d_in[3];
    const float* Wh   = (const float*)d_in[4];
    const float* logr = (const float*)d_in[5];
    const float* b    = (const float*)d_in[6];
    const float* u0   = (const float*)d_in[7];
    float* out = (float*)d_out;

    gemm_kernel<<<dim3(DIM/128, (T_STEPS*BATCH)/128), 256>>>(x, Wx, b);

    cudaFuncSetAttribute(rnn_kernel, cudaFuncAttributeMaxDynamicSharedMemorySize,
                         SMEM_RNN_BYTES);
    rnn_kernel<<<NCTA, NTHR, SMEM_RNN_BYTES>>>(z, h0, Wh, logr, u0, out);
}